// round 16
// baseline (speedup 1.0000x reference)
#include <cuda_runtime.h>

// Problem constants (from reference)
#define NWIN   16
#define NSTEP  16          // 1 + NG + NF
#define NP     256         // NWIN * NSTEP pairs
#define TT     400
#define DIMV   64
#define NG     5
#define NF     10
#define BIG_F   1e10f
#define TILE    80         // 400 = 5 * 80
#define SSTRIDE 84         // k-major smem row stride

// fused geometry: 13 dp warps (416 thr) + 8 producer warps (256 thr)
#define DPW  13
#define DPG  8
#define DPT  416
#define PRT  256
#define FTHREADS (DPT + PRT)   // 672

// exp/log base-2 folded constants:
//   exp((m-x)/g) = exp2((m-x) * C1),  C1 = log2(e)/g
//   g*ln(s)      = C2 * log2(s),      C2 = g*ln(2)
#define C1_F 0.28853900817779268f
#define C2_F 3.4657359027997265f

// Scratch: __device__ globals (no cudaMalloc allowed)
__device__ float g_D[(size_t)NP * TT * TT];   // 163.84 MB cost matrices
__device__ float g_norm[NP * TT];             // per-row squared norms
__device__ float g_dists[NP];                 // soft-DTW distances

// ncu capture = launch index 3; probes pad indices 1-2 so fused_kernel sits
// at the profiled slot.
__global__ void probe0_kernel() {}
__global__ void probe1_kernel() {}

// ---------------------------------------------------------------------------
// Phase 0: row squared norms. One warp per (pair,row); 2 loads + shuffle tree.
// ---------------------------------------------------------------------------
__global__ void norm_kernel(const float* __restrict__ data) {
    int w = blockIdx.x * (blockDim.x >> 5) + (threadIdx.x >> 5);
    int lane = threadIdx.x & 31;
    const float* row = data + (size_t)w * DIMV;
    float v0 = row[lane];
    float v1 = row[lane + 32];
    float s = v0 * v0 + v1 * v1;
    #pragma unroll
    for (int o = 16; o > 0; o >>= 1) s += __shfl_xor_sync(0xffffffffu, s, o);
    if (lane == 0) g_norm[w] = s;
}

// ---------------------------------------------------------------------------
// soft-DTW cell: median trick (the min's exp2 term is exactly 1 ->
// bitwise-identical 3-term sum with only 2 EX2) + MUFU LG2. ~15 instr.
// NOTE: keep (m-x)*C1 (FADD->FMUL); fmaf refactor can round BIG-BIG
// exponents to +-128 -> exp2=inf -> -inf poison. exp2 args <= 0 always.
// ---------------------------------------------------------------------------
__device__ __forceinline__ float sdtw_cell(float a, float b, float c, float d) {
    float mn  = fminf(a, b);
    float mx  = fmaxf(a, b);
    float m   = fminf(mn, c);                    // min3
    float med = fmaxf(fminf(mx, c), mn);         // median3
    float mx3 = fmaxf(mx, c);                    // max3
    float s = 1.0f + exp2f((m - med) * C1_F) + exp2f((m - mx3) * C1_F);
    return d + m - C2_F * __log2f(s);
}

// ---------------------------------------------------------------------------
// FUSED kernel: one CTA per pair. Producer warps compute the pair's D tiles
// while consumer warps run the soft-DTW wavefront on them — d's pure-FMA work
// fills the issue/FMA slots dp leaves idle (dp alone: 37% issue, 9.8% FMA).
//
// Producer (threads 416..671, 256 thr): tiles in band-diagonal order
// (bd = ti+tj ascending), box-pruned; per tile: bar(2) / load As,Bs k-major /
// bar(2) / 16x16 threads x 5x5 microtile -> STG to g_D. After each band:
// bar(2), then pt==0 does threadfence + bands_done = bd+1 (release).
//
// Consumer (threads 0..415): exact round-13 dp (DPG=8, D double-buffer,
// interior fast path, band skip), with __syncthreads -> bar.sync 1,416 and
// __ldg -> plain LDG (data is self-CTA-written). Before each D load batch a
// per-warp watermark checks bands_done >= ti2+tjmax+1 (acquire: volatile poll
// + threadfence_block), polling only when the needed band advances.
//
// Safety: producers never wait on consumers; bands_done monotonically reaches
// 9 (pruned tiles counted done); any VALID cell (i<=la, j<=lb) maps to an
// unpruned tile, so garbage reads feed masked cells only (select, no NaN
// propagation into rn). Named barriers: id1/416 dp-only, id2/256 prod-only;
// one full __syncthreads at init. D accumulation is k-ascending FMA ->
// bitwise-identical to the standalone d_kernel.
// ---------------------------------------------------------------------------
__global__ __launch_bounds__(FTHREADS, 2) void fused_kernel(
        const float* __restrict__ data, const int* __restrict__ lens) {
    int p  = blockIdx.x;
    int la = lens[p & ~(NSTEP - 1)];
    int lb = lens[p];
    int t  = threadIdx.x;

    __shared__ float As[DIMV][SSTRIDE];   // k-major: As[k][row]
    __shared__ float Bs[DIMV][SSTRIDE];
    __shared__ float bnd[2][DPW][DPG];
    __shared__ int   bands_done;

    if (t < 2 * DPW * DPG) ((float*)bnd)[t] = BIG_F;
    if (t == 0) bands_done = 0;
    __syncthreads();                      // the only full-CTA barrier

    float* Dp = g_D + (size_t)p * TT * TT;

    if (t >= DPT) {
        // ======================= producer =======================
        int pt = t - DPT;
        const float* A = data + (size_t)(p & ~(NSTEP - 1)) * TT * DIMV;
        const float* B = data + (size_t)p * TT * DIMV;
        const float* nA0 = g_norm + (p & ~(NSTEP - 1)) * TT;
        const float* nB0 = g_norm + p * TT;
        int nti = (la + TILE - 1) / TILE;
        int ntj = (lb + TILE - 1) / TILE;
        int tx = pt & 15, ty = pt >> 4;   // 16x16 grid, 5x5 microtile

        for (int bd = 0; bd <= 8; bd++) {
            int tlo = bd > 4 ? bd - 4 : 0;
            int thi = bd < 4 ? bd : 4;
            for (int ti = tlo; ti <= thi; ti++) {
                int tj = bd - ti;
                if (ti >= nti || tj >= ntj) continue;   // pruned tile

                asm volatile("bar.sync 2, %0;" :: "n"(PRT) : "memory"); // buffers free
                for (int it = pt; it < TILE * 16; it += PRT) {
                    int row = it >> 4, c4 = (it & 15) * 4;
                    float4 va = *(const float4*)(A + (size_t)(ti * TILE + row) * DIMV + c4);
                    float4 vb = *(const float4*)(B + (size_t)(tj * TILE + row) * DIMV + c4);
                    As[c4 + 0][row] = va.x; As[c4 + 1][row] = va.y;
                    As[c4 + 2][row] = va.z; As[c4 + 3][row] = va.w;
                    Bs[c4 + 0][row] = vb.x; Bs[c4 + 1][row] = vb.y;
                    Bs[c4 + 2][row] = vb.z; Bs[c4 + 3][row] = vb.w;
                }
                asm volatile("bar.sync 2, %0;" :: "n"(PRT) : "memory"); // tiles loaded

                float acc[5][5];
                #pragma unroll
                for (int r = 0; r < 5; r++)
                    #pragma unroll
                    for (int c = 0; c < 5; c++) acc[r][c] = 0.0f;
                #pragma unroll 4
                for (int k = 0; k < DIMV; k++) {
                    float a[5], b[5];
                    #pragma unroll
                    for (int r = 0; r < 5; r++) a[r] = As[k][ty * 5 + r];
                    #pragma unroll
                    for (int c = 0; c < 5; c++) b[c] = Bs[k][tx * 5 + c];
                    #pragma unroll
                    for (int r = 0; r < 5; r++)
                        #pragma unroll
                        for (int c = 0; c < 5; c++) acc[r][c] += a[r] * b[c];
                }
                float na[5], nb[5];
                #pragma unroll
                for (int r = 0; r < 5; r++) na[r] = nA0[ti * TILE + ty * 5 + r];
                #pragma unroll
                for (int c = 0; c < 5; c++) nb[c] = nB0[tj * TILE + tx * 5 + c];
                #pragma unroll
                for (int r = 0; r < 5; r++) {
                    size_t gi = (size_t)(ti * TILE + ty * 5 + r) * TT
                              + tj * TILE + tx * 5;
                    #pragma unroll
                    for (int c = 0; c < 5; c++)
                        Dp[gi + c] = na[r] + nb[c] - 2.0f * acc[r][c];
                }
            }
            // publish band bd (release)
            asm volatile("bar.sync 2, %0;" :: "n"(PRT) : "memory");
            if (pt == 0) {
                __threadfence_block();
                *((volatile int*)&bands_done) = bd + 1;
            }
        }
        return;
    }

    // ======================= dp consumer =======================
    int lane = t & 31;
    int w    = t >> 5;
    int i    = t + 1;                 // DP row owned by this lane (1..416)
    int kmax = la + lb;
    float inv = 1.0f / (float)kmax;

    const float* Drow = Dp + (size_t)((i - 1 < TT - 1) ? (i - 1) : (TT - 1)) * TT;
    bool rowok   = (i <= la);
    bool lastrow = (i == la);

    float r1   = BIG_F;                       // R[i][1-i] (j<=0 -> BIG)
    float r1m1 = BIG_F;                       // R[i-1][2-i]
    float r2m1 = (t == 0) ? 0.0f : BIG_F;     // R[0][0]=0 seeds warp0 lane0

    int wstart = 32 * w + 1;
    int wend   = 32 * w + 32 + lb;
    int smax   = (DPW - 1) + (kmax - 2) / DPG;
    int w32    = 32 * w;
    bool fullrows = (w32 + 32 <= la);
    int ti2w = ((w32 + 31 < TT - 1) ? (w32 + 31) : (TT - 1)) / TILE;
    int seen = 0;                             // bands_done watermark confirmed

    // wait until all tiles needed by a load batch starting at diag a0 exist
    #define WAIT_TILES(a0)  do {                                              \
        int _mc = (a0) - w32 + (DPG - 3);                                     \
        if (_mc > TT - 1) _mc = TT - 1;                                       \
        if (_mc < 0) _mc = 0;                                                 \
        int _need = ti2w + _mc / TILE + 1;                                    \
        if (_need > seen) {                                                   \
            while (*((volatile int*)&bands_done) < _need) __nanosleep(64);    \
            __threadfence_block();                                            \
            seen = _need;                                                     \
        }                                                                     \
    } while (0)

    int  acur   = 2 - w * DPG;
    bool actcur = (0 >= w) && (acur <= kmax)
               && (acur + DPG - 1 >= wstart) && (acur <= wend);

    float dv[DPG];
    if (actcur) {                              // prologue load
        WAIT_TILES(acur);
        int c0 = acur - i - 1;
        if (acur - w32 - 33 >= 0 && acur - w32 + (DPG - 3) <= TT - 1) {
            #pragma unroll
            for (int d = 0; d < DPG; d++) dv[d] = Drow[c0 + d];
        } else {
            #pragma unroll
            for (int d = 0; d < DPG; d++) {
                int c = c0 + d;
                c = c < 0 ? 0 : (c > TT - 1 ? TT - 1 : c);
                dv[d] = Drow[c];
            }
        }
    }

    for (int s = 0; s <= smax; s++) {
        // ---- prefetch D for step s+1 (issued before this step's chain) ----
        int  anext   = acur + DPG;
        bool actnext = (s + 1 >= w) && (anext <= kmax)
                    && (anext + DPG - 1 >= wstart) && (anext <= wend);
        float dvn[DPG];
        if (actnext) {
            WAIT_TILES(anext);
            int c0n = anext - i - 1;
            if (anext - w32 - 33 >= 0 && anext - w32 + (DPG - 3) <= TT - 1) {
                #pragma unroll
                for (int d = 0; d < DPG; d++) dvn[d] = Drow[c0n + d];
            } else {
                #pragma unroll
                for (int d = 0; d < DPG; d++) {
                    int c = c0n + d;
                    c = c < 0 ? 0 : (c > TT - 1 ? TT - 1 : c);
                    dvn[d] = Drow[c];
                }
            }
        }

        // ---- process step s ----
        if (actcur) {
            const float* bprev = bnd[(s + 1) & 1][w > 0 ? w - 1 : 0];
            float*       bout  = bnd[s & 1][w];

            bool fast = fullrows && (acur >= w32 + 33)
                     && (acur + DPG - 1 <= lb + w32 + 1)
                     && (acur + DPG - 1 < kmax);

            if (fast) {
                #pragma unroll
                for (int d = 0; d < DPG; d++) {
                    float rn = sdtw_cell(r2m1, r1m1, r1, dv[d]);
                    if (lane == 31) bout[d] = rn;
                    r2m1 = r1m1;
                    float sh = __shfl_up_sync(0xffffffffu, rn, 1);
                    float b0 = (w == 0) ? BIG_F : bprev[d];
                    r1m1 = (lane == 0) ? b0 : sh;
                    r1 = rn;
                }
            } else {
                int n = kmax - acur + 1; if (n > DPG) n = DPG;
                #pragma unroll
                for (int d = 0; d < DPG; d++) {
                    if (d < n) {                   // warp-uniform
                        int k = acur + d;
                        int j = k - i;
                        bool valid = rowok && (j >= 1) && (j <= lb);
                        float v  = sdtw_cell(r2m1, r1m1, r1, dv[d]);
                        float rn = valid ? v : BIG_F;
                        if (lastrow && j == lb)
                            g_dists[p] = rn * inv;         // R[la][lb]/(la+lb)
                        if (lane == 31) bout[d] = rn;
                        r2m1 = r1m1;
                        float sh = __shfl_up_sync(0xffffffffu, rn, 1);
                        float b0 = (w == 0) ? BIG_F : bprev[d];
                        r1m1 = (lane == 0) ? b0 : sh;
                        r1 = rn;
                    }
                }
            }
        }
        asm volatile("bar.sync 1, %0;" :: "n"(DPT) : "memory");

        // ---- rotate double buffer ----
        acur   = anext;
        actcur = actnext;
        #pragma unroll
        for (int d = 0; d < DPG; d++) dv[d] = dvn[d];
    }
    #undef WAIT_TILES
}

// ---------------------------------------------------------------------------
// Phase 3: contrastive loss over 16 windows -> scalar mean.
// ---------------------------------------------------------------------------
__global__ void reduce_kernel(const float* __restrict__ margin,
                              float* __restrict__ out) {
    __shared__ float lv[NWIN];
    int tid = threadIdx.x;
    if (tid < NWIN) {
        const float* dw = g_dists + tid * NSTEP;
        float daa = dw[0];
        float mg  = margin[0];
        float ssum = 0.0f;
        int nz = 1;
        #pragma unroll
        for (int s = 1; s <= NG; s++) {
            float v = dw[s] - daa;
            ssum += v;
            nz += (v != 0.0f);
        }
        #pragma unroll
        for (int s = 1 + NG; s < 1 + NG + NF; s++) {
            float v = mg - (dw[s] - daa);
            v = fmaxf(v, 0.0f);
            ssum += v;
            nz += (v != 0.0f);
        }
        lv[tid] = ssum / (float)nz;
    }
    __syncthreads();
    if (tid == 0) {
        float tsum = 0.0f;
        #pragma unroll
        for (int w = 0; w < NWIN; w++) tsum += lv[w];
        out[0] = tsum * (1.0f / NWIN);
    }
}

// ---------------------------------------------------------------------------
extern "C" void kernel_launch(void* const* d_in, const int* in_sizes, int n_in,
                              void* d_out, int out_size) {
    const float* data   = (const float*)d_in[0];
    const float* margin = (const float*)d_in[1];
    const int*   lens   = (const int*)d_in[2];
    float*       out    = (float*)d_out;

    norm_kernel<<<(NP * TT) / 8, 256>>>(data);             // idx 0
    probe0_kernel<<<1, 32>>>();                            // idx 1 (pad)
    probe1_kernel<<<1, 32>>>();                            // idx 2 (pad)
    fused_kernel<<<NP, FTHREADS>>>(data, lens);            // idx 3 <- ncu capture
    reduce_kernel<<<1, 32>>>(margin, out);                 // idx 4
}

// round 17
// speedup vs baseline: 1.4217x; 1.4217x over previous
#include <cuda_runtime.h>

// Problem constants (from reference)
#define NWIN   16
#define NSTEP  16          // 1 + NG + NF
#define NP     256         // NWIN * NSTEP pairs
#define TT     400
#define DIMV   64
#define NG     5
#define NF     10
#define BIG_F   1e10f
#define TILE    80         // 400 = 5 * 80, zero edge waste
#define SSTRIDE 84         // k-major smem row stride (16B-aligned)
#define DTHREADS 200       // 10(ty) x 20(tx) threads, 8x4 microtile

// dp geometry: 13 warps x 32 rows/warp = 416 rows; G diagonals per super-step
// DPG=8 is the measured sweet spot (16 doubled the pipeline-fill term and
// regs; fusion with the D producer serialized d's grid parallelism into the
// dp critical path -- both regressed).
#define DPW  13
#define DPG  8

// exp/log base-2 folded constants:
//   exp((m-x)/g) = exp2((m-x) * C1),  C1 = log2(e)/g
//   g*ln(s)      = C2 * log2(s),      C2 = g*ln(2)
#define C1_F 0.28853900817779268f
#define C2_F 3.4657359027997265f

// Scratch: __device__ globals (no cudaMalloc allowed)
__device__ float g_D[(size_t)NP * TT * TT];   // 163.84 MB cost matrices
__device__ float g_norm[NP * TT];             // per-row squared norms
__device__ float g_dists[NP];                 // soft-DTW distances

// ncu capture = launch index 3 of the call; probe0 pads index 2 so dp_kernel
// stays at the profiled slot.
__global__ void probe0_kernel() {}

// ---------------------------------------------------------------------------
// Phase 0: row squared norms. One warp per (pair,row); 2 loads + shuffle tree.
// ---------------------------------------------------------------------------
__global__ void norm_kernel(const float* __restrict__ data) {
    int w = blockIdx.x * (blockDim.x >> 5) + (threadIdx.x >> 5);
    int lane = threadIdx.x & 31;
    const float* row = data + (size_t)w * DIMV;
    float v0 = row[lane];
    float v1 = row[lane + 32];
    float s = v0 * v0 + v1 * v1;
    #pragma unroll
    for (int o = 16; o > 0; o >>= 1) s += __shfl_xor_sync(0xffffffffu, s, o);
    if (lane == 0) g_norm[w] = s;
}

// ---------------------------------------------------------------------------
// Phase 1: D[p][i][j] = na[i] + nb[j] - 2 * dot(A_i, B_j)
// 80x80 tile per CTA, 200 threads, 8x4 microtile (round-14 win: d is
// LDS-throughput-bound; 8x4 is 1.5B/FMA vs 2B/FMA at 4x4). k-major smem,
// 3x LDS.128 + 32 FFMA per k per thread. Box-pruned tiles.
// ---------------------------------------------------------------------------
__global__ __launch_bounds__(DTHREADS) void d_kernel(const float* __restrict__ data,
                                                     const int* __restrict__ lens) {
    int p  = blockIdx.z;
    int ti = blockIdx.y, tj = blockIdx.x;

    int la = __ldg(&lens[p & ~(NSTEP - 1)]);
    int lb = __ldg(&lens[p]);
    if (ti * TILE >= la || tj * TILE >= lb) return;   // dead tile

    const float* A = data + (size_t)(p & ~(NSTEP - 1)) * TT * DIMV;  // window anchor
    const float* B = data + (size_t)p * TT * DIMV;

    __shared__ float As[DIMV][SSTRIDE];   // k-major: As[k][row]
    __shared__ float Bs[DIMV][SSTRIDE];

    int tid = threadIdx.x;
    for (int it = tid; it < TILE * 16; it += DTHREADS) {
        int row = it >> 4, c4 = (it & 15) * 4;
        float4 va = *(const float4*)(A + (size_t)(ti * TILE + row) * DIMV + c4);
        float4 vb = *(const float4*)(B + (size_t)(tj * TILE + row) * DIMV + c4);
        As[c4 + 0][row] = va.x; As[c4 + 1][row] = va.y;
        As[c4 + 2][row] = va.z; As[c4 + 3][row] = va.w;
        Bs[c4 + 0][row] = vb.x; Bs[c4 + 1][row] = vb.y;
        Bs[c4 + 2][row] = vb.z; Bs[c4 + 3][row] = vb.w;
    }
    __syncthreads();

    int tx = tid % 20, ty = tid / 20;   // 10x20 grid of 8x4 microtiles
    float acc[8][4];
    #pragma unroll
    for (int r = 0; r < 8; r++)
        #pragma unroll
        for (int c = 0; c < 4; c++) acc[r][c] = 0.0f;

    #pragma unroll 2
    for (int k = 0; k < DIMV; k++) {
        float4 a0 = *(const float4*)&As[k][ty * 8];
        float4 a1 = *(const float4*)&As[k][ty * 8 + 4];
        float4 b4 = *(const float4*)&Bs[k][tx * 4];
        float a[8] = {a0.x, a0.y, a0.z, a0.w, a1.x, a1.y, a1.z, a1.w};
        float b[4] = {b4.x, b4.y, b4.z, b4.w};
        #pragma unroll
        for (int r = 0; r < 8; r++)
            #pragma unroll
            for (int c = 0; c < 4; c++) acc[r][c] += a[r] * b[c];
    }

    const float* nA = g_norm + (p & ~(NSTEP - 1)) * TT + ti * TILE + ty * 8;
    const float* nB = g_norm + p * TT + tj * TILE + tx * 4;
    float na[8], nb[4];
    #pragma unroll
    for (int r = 0; r < 8; r++) na[r] = nA[r];
    #pragma unroll
    for (int c = 0; c < 4; c++) nb[c] = nB[c];

    float* Dp = g_D + (size_t)p * TT * TT;
    #pragma unroll
    for (int r = 0; r < 8; r++) {
        int gi = ti * TILE + ty * 8 + r;
        int gj = tj * TILE + tx * 4;
        float4 o;
        o.x = na[r] + nb[0] - 2.0f * acc[r][0];
        o.y = na[r] + nb[1] - 2.0f * acc[r][1];
        o.z = na[r] + nb[2] - 2.0f * acc[r][2];
        o.w = na[r] + nb[3] - 2.0f * acc[r][3];
        *(float4*)(Dp + (size_t)gi * TT + gj) = o;
    }
}

// ---------------------------------------------------------------------------
// soft-DTW cell: median trick (the min's exp2 term is exactly 1 ->
// bitwise-identical 3-term sum with only 2 EX2) + MUFU LG2. ~15 instr.
// NOTE: keep (m-x)*C1 (FADD->FMUL); fmaf refactor can round BIG-BIG
// exponents to +-128 -> exp2=inf -> -inf poison. exp2 args <= 0 always.
// ---------------------------------------------------------------------------
__device__ __forceinline__ float sdtw_cell(float a, float b, float c, float d) {
    float mn  = fminf(a, b);
    float mx  = fmaxf(a, b);
    float m   = fminf(mn, c);                    // min3
    float med = fmaxf(fminf(mx, c), mn);         // median3
    float mx3 = fmaxf(mx, c);                    // max3
    float s = 1.0f + exp2f((m - med) * C1_F) + exp2f((m - mx3) * C1_F);
    return d + m - C2_F * __log2f(s);
}

// ---------------------------------------------------------------------------
// Phase 2: pipelined warp-shuffle soft-DTW wavefront (round-13 config, the
// measured best: dp=162us). One CTA per pair, 416 threads (13 warps).
// Lane owns row i = tid+1. Warp w is skewed DPG diagonals behind warp w-1;
// super-step s: warp w does diags [2+(s-w)G, +G).
//
// Register state per lane (before processing diag k):
//   r1   = R[i  ][k-1-i],  r1m1 = R[i-1][k-i],  r2m1 = R[i-1][k-1-i]
// Cross-warp boundary (lane31 -> next warp's lane0) via double-buffered smem.
// Band skip: warp w only executes steps overlapping diags [32w+1, 32w+32+lb].
// D stream double-buffered across the barrier. Interior fast path (all cells
// valid, no capture) drops masking plumbing; edge steps take the generic
// path. Values computed are identical on both paths.
//
// NEW (this round): boundary PRELOAD — bprev[0..DPG) is read into registers
// once at the top of each step (values are final after the previous barrier;
// bout writes go to the opposite parity, but the compiler cannot prove that
// aliasing). This hoists 8 independent LDS out of the serial cell chain,
// removing a lat-29 LDS from lane0's critical path in every cell.
// ---------------------------------------------------------------------------
__global__ __launch_bounds__(416) void dp_kernel(const int* __restrict__ lens) {
    int p  = blockIdx.x;
    int la = lens[p & ~(NSTEP - 1)];
    int lb = lens[p];
    int t  = threadIdx.x;
    int lane = t & 31;
    int w    = t >> 5;
    int i    = t + 1;                 // DP row owned by this lane (1..416)
    int kmax = la + lb;
    float inv = 1.0f / (float)kmax;

    __shared__ float bnd[2][DPW][DPG];
    if (t < 2 * DPW * DPG) ((float*)bnd)[t] = BIG_F;
    __syncthreads();

    const float* Drow = g_D + (size_t)p * TT * TT
                      + (size_t)((i - 1 < TT - 1) ? (i - 1) : (TT - 1)) * TT;
    bool rowok   = (i <= la);
    bool lastrow = (i == la);

    float r1   = BIG_F;                       // R[i][1-i] (j<=0 -> BIG)
    float r1m1 = BIG_F;                       // R[i-1][2-i]
    float r2m1 = (t == 0) ? 0.0f : BIG_F;     // R[0][0]=0 seeds warp0 lane0

    int wstart = 32 * w + 1;                  // first diag this warp matters for
    int wend   = 32 * w + 32 + lb;            // last diag with any valid cell
    int smax   = (DPW - 1) + (kmax - 2) / DPG;
    int w32    = 32 * w;
    bool fullrows = (w32 + 32 <= la);

    // current-step state: acur = first diag of step s for this warp
    int  acur   = 2 - w * DPG;                // a at s=0
    bool actcur = (0 >= w) && (acur <= kmax)
               && (acur + DPG - 1 >= wstart) && (acur <= wend);

    float dv[DPG];
    if (actcur) {                              // prologue load (exposed once)
        int c0 = acur - i - 1;
        if (acur - w32 - 33 >= 0 && acur - w32 + (DPG - 3) <= TT - 1) {
            #pragma unroll
            for (int d = 0; d < DPG; d++) dv[d] = __ldg(&Drow[c0 + d]);
        } else {
            #pragma unroll
            for (int d = 0; d < DPG; d++) {
                int c = c0 + d;
                c = c < 0 ? 0 : (c > TT - 1 ? TT - 1 : c);
                dv[d] = __ldg(&Drow[c]);
            }
        }
    }

    for (int s = 0; s <= smax; s++) {
        // ---- prefetch D for step s+1 (issued before this step's chain) ----
        int  anext   = acur + DPG;
        bool actnext = (s + 1 >= w) && (anext <= kmax)
                    && (anext + DPG - 1 >= wstart) && (anext <= wend);
        float dvn[DPG];
        if (actnext) {
            int c0n = anext - i - 1;
            if (anext - w32 - 33 >= 0 && anext - w32 + (DPG - 3) <= TT - 1) {
                #pragma unroll
                for (int d = 0; d < DPG; d++) dvn[d] = __ldg(&Drow[c0n + d]);
            } else {
                #pragma unroll
                for (int d = 0; d < DPG; d++) {
                    int c = c0n + d;
                    c = c < 0 ? 0 : (c > TT - 1 ? TT - 1 : c);
                    dvn[d] = __ldg(&Drow[c]);
                }
            }
        }

        // ---- process step s ----
        if (actcur) {
            float* bout = bnd[s & 1][w];

            // boundary preload: final since the previous barrier; parity-
            // disjoint from bout writes. 8 independent LDS, off the chain.
            float bpre[DPG];
            if (w > 0) {
                const float* bprev = bnd[(s + 1) & 1][w - 1];
                #pragma unroll
                for (int d = 0; d < DPG; d++) bpre[d] = bprev[d];
            } else {
                #pragma unroll
                for (int d = 0; d < DPG; d++) bpre[d] = BIG_F;
            }

            bool fast = fullrows && (acur >= w32 + 33)
                     && (acur + DPG - 1 <= lb + w32 + 1)
                     && (acur + DPG - 1 < kmax);

            if (fast) {
                // interior: every cell valid, no capture, n == DPG
                #pragma unroll
                for (int d = 0; d < DPG; d++) {
                    float rn = sdtw_cell(r2m1, r1m1, r1, dv[d]);
                    if (lane == 31) bout[d] = rn;
                    r2m1 = r1m1;
                    float sh = __shfl_up_sync(0xffffffffu, rn, 1);
                    r1m1 = (lane == 0) ? bpre[d] : sh;
                    r1 = rn;
                }
            } else {
                int n = kmax - acur + 1; if (n > DPG) n = DPG;
                #pragma unroll
                for (int d = 0; d < DPG; d++) {
                    if (d < n) {                   // warp-uniform
                        int k = acur + d;
                        int j = k - i;
                        bool valid = rowok && (j >= 1) && (j <= lb);
                        float v  = sdtw_cell(r2m1, r1m1, r1, dv[d]);
                        float rn = valid ? v : BIG_F;
                        if (lastrow && j == lb)
                            g_dists[p] = rn * inv;         // R[la][lb]/(la+lb)
                        if (lane == 31) bout[d] = rn;      // boundary to warp w+1
                        r2m1 = r1m1;
                        float sh = __shfl_up_sync(0xffffffffu, rn, 1);
                        r1m1 = (lane == 0) ? bpre[d] : sh;
                        r1 = rn;
                    }
                }
            }
        }
        __syncthreads();

        // ---- rotate double buffer ----
        acur   = anext;
        actcur = actnext;
        #pragma unroll
        for (int d = 0; d < DPG; d++) dv[d] = dvn[d];
    }
}

// ---------------------------------------------------------------------------
// Phase 3: contrastive loss over 16 windows -> scalar mean.
// ---------------------------------------------------------------------------
__global__ void reduce_kernel(const float* __restrict__ margin,
                              float* __restrict__ out) {
    __shared__ float lv[NWIN];
    int tid = threadIdx.x;
    if (tid < NWIN) {
        const float* dw = g_dists + tid * NSTEP;
        float daa = dw[0];
        float mg  = margin[0];
        float ssum = 0.0f;
        int nz = 1;
        #pragma unroll
        for (int s = 1; s <= NG; s++) {
            float v = dw[s] - daa;
            ssum += v;
            nz += (v != 0.0f);
        }
        #pragma unroll
        for (int s = 1 + NG; s < 1 + NG + NF; s++) {
            float v = mg - (dw[s] - daa);
            v = fmaxf(v, 0.0f);
            ssum += v;
            nz += (v != 0.0f);
        }
        lv[tid] = ssum / (float)nz;
    }
    __syncthreads();
    if (tid == 0) {
        float tsum = 0.0f;
        #pragma unroll
        for (int w = 0; w < NWIN; w++) tsum += lv[w];
        out[0] = tsum * (1.0f / NWIN);
    }
}

// ---------------------------------------------------------------------------
extern "C" void kernel_launch(void* const* d_in, const int* in_sizes, int n_in,
                              void* d_out, int out_size) {
    const float* data   = (const float*)d_in[0];
    const float* margin = (const float*)d_in[1];
    const int*   lens   = (const int*)d_in[2];
    float*       out    = (float*)d_out;

    norm_kernel<<<(NP * TT) / 8, 256>>>(data);             // idx 0
    d_kernel<<<dim3(5, 5, NP), DTHREADS>>>(data, lens);    // idx 1
    probe0_kernel<<<1, 32>>>();                            // idx 2 (pad)
    dp_kernel<<<NP, 416>>>(lens);                          // idx 3 <- ncu capture slot
    reduce_kernel<<<1, 32>>>(margin, out);                 // idx 4
}